// round 14
// baseline (speedup 1.0000x reference)
#include <cuda_runtime.h>
#include <cstdint>

// FPS on GB300, round 9: minimal serial chain.
// 128 plain CTAs (16 per batch). Coords register-resident. ONE syncthreads
// per step; no hub; no park barrier; no clusters.
// Exchange = one 8-byte word per CTA per step in L2:
//   packed = vbits<<32 | (s+1)<<17 | gi      (gi<2^17, s+1<2^13)
// 8B relaxed ld/st are single-copy atomic -> tag and payload travel together,
// no acquire/release needed. Slots double-buffered by parity (g_ex[b][p][r]).
// Every warp redundantly: CTA-reduce (REDUX over smem wv/wi), publish
// (idempotent identical store), poll 16 peer words, reduce, then read winner
// coords from pts[] (L2-resident; issued per-lane BEFORE the reduce so the
// load overlaps it), and proceeds immediately into the next update.
// WAR chain: any warp reads slot[p](s) after its poll(s); a peer overwrites
// slot[p] at publish(s+2), which follows its bar(s+2), which follows all its
// warps' reduce(s+1), whose polls required MY tag(s+1), published after MY
// bar(s+1), which follows all MY warps' reads of slot[p](s).  Closed.
// Cross-run staleness benign: kernel is deterministic, so a stale word for
// (step,parity) from a previous replay is bit-identical to the fresh one.
// Bit-exactness vs reference (rel_err 0.0 in rounds 1-8): add.rn/mul.rn.f32x2
// packed math (== scalar rn ops), mul-then-add sum order, first-index
// tie-break at every reduce level.

#define NPTS   131072
#define BATCH  8
#define NSAMP  4096
#define GRP    16
#define NT     512
#define PPC    (NPTS / GRP)          // 8192
#define QPT    (PPC / (4 * NT))      // 4 quads -> 16 pts/thread
#define BIGF   1e10f

// One u64 per CTA per parity: [batch][parity][rank].
__device__ unsigned long long g_ex[BATCH][2][GRP];

#define ADD2(o, a, b) asm("add.rn.f32x2 %0, %1, %2;" : "=l"(o) : "l"(a), "l"(b))
#define MUL2(o, a, b) asm("mul.rn.f32x2 %0, %1, %2;" : "=l"(o) : "l"(a), "l"(b))
#define PACK2(o, lo, hi) asm("mov.b64 %0, {%1, %2};" : "=l"(o) : "f"(lo), "f"(hi))
#define UNPACK2(lo, hi, in) asm("mov.b64 {%0, %1}, %2;" : "=f"(lo), "=f"(hi) : "l"(in))

static __device__ __forceinline__ void st_rlx_gpu(unsigned long long* p,
                                                  unsigned long long v) {
    asm volatile("st.relaxed.gpu.global.u64 [%0], %1;" :: "l"(p), "l"(v) : "memory");
}
static __device__ __forceinline__ unsigned long long ld_rlx_gpu(
    const unsigned long long* p) {
    unsigned long long v;
    asm volatile("ld.relaxed.gpu.global.u64 %0, [%1];" : "=l"(v) : "l"(p) : "memory");
    return v;
}

__global__ void __launch_bounds__(NT, 1)
fps9(const float* __restrict__ pts, float* __restrict__ out)
{
    __shared__ unsigned wv[32];   // per-warp best value bits (lanes 16..31 pad)
    __shared__ unsigned wi[32];   // per-warp best local idx

    const int tid  = threadIdx.x;
    const int lane = tid & 31;
    const int warp = tid >> 5;
    const int b    = blockIdx.x >> 4;       // batch
    const int rank = blockIdx.x & 15;
    const float* P = pts + (size_t)b * NPTS * 3;
    const int base = rank * PPC;

    // Register-resident coords, packed f32x2 (16 pts per thread).
    unsigned long long Xr[2 * QPT], Yr[2 * QPT], Zr[2 * QPT];
#pragma unroll
    for (int j = 0; j < QPT; j++) {
        const int i0 = 4 * (j * NT + tid);
        float x[4], y[4], z[4];
#pragma unroll
        for (int k = 0; k < 4; k++) {
            const float* g = P + (size_t)(base + i0 + k) * 3;
            x[k] = g[0]; y[k] = g[1]; z[k] = g[2];
        }
        PACK2(Xr[2 * j], x[0], x[1]); PACK2(Xr[2 * j + 1], x[2], x[3]);
        PACK2(Yr[2 * j], y[0], y[1]); PACK2(Yr[2 * j + 1], y[2], y[3]);
        PACK2(Zr[2 * j], z[0], z[1]); PACK2(Zr[2 * j + 1], z[2], z[3]);
    }
    if (tid < 32) { wv[tid] = 0u; wi[tid] = 0xffffffffu; }  // pad warps 16..31

    float4 md[QPT];
#pragma unroll
    for (int j = 0; j < QPT; j++) md[j] = make_float4(BIGF, BIGF, BIGF, BIGF);

    __syncthreads();   // wv/wi pad visible

    float lx = P[0], ly = P[1], lz = P[2];   // reference: last_idx init = 0

    for (int s = 0; s < NSAMP; s++) {
        // Reference scan emits last_idx BEFORE the update.
        if (rank == 0 && tid == 0) {
            float* o = out + ((size_t)b * NSAMP + s) * 3;
            o[0] = lx; o[1] = ly; o[2] = lz;
        }

        unsigned long long NX, NY, NZ;
        {
            float nx = -lx, ny = -ly, nz = -lz;  // x + (-l) == x - l bit-exact
            PACK2(NX, nx, nx); PACK2(NY, ny, ny); PACK2(NZ, nz, nz);
        }

        // ---- distance update (packed f32x2; mul-then-add order = reference) ----
#pragma unroll
        for (int j = 0; j < QPT; j++) {
            unsigned long long xa = Xr[2 * j], xb = Xr[2 * j + 1];
            unsigned long long ya = Yr[2 * j], yb = Yr[2 * j + 1];
            unsigned long long za = Zr[2 * j], zb = Zr[2 * j + 1];
            unsigned long long sa, sb;
            ADD2(xa, xa, NX); MUL2(xa, xa, xa);
            ADD2(ya, ya, NY); MUL2(ya, ya, ya);
            ADD2(za, za, NZ); MUL2(za, za, za);
            ADD2(sa, xa, ya);          // (dx^2 + dy^2)
            ADD2(sa, sa, za);          // + dz^2 — same order as jnp.sum
            ADD2(xb, xb, NX); MUL2(xb, xb, xb);
            ADD2(yb, yb, NY); MUL2(yb, yb, yb);
            ADD2(zb, zb, NZ); MUL2(zb, zb, zb);
            ADD2(sb, xb, yb);
            ADD2(sb, sb, zb);
            float d0, d1, d2, d3;
            UNPACK2(d0, d1, sa);
            UNPACK2(d2, d3, sb);
            md[j].x = fminf(md[j].x, d0);
            md[j].y = fminf(md[j].y, d1);
            md[j].z = fminf(md[j].z, d2);
            md[j].w = fminf(md[j].w, d3);
        }

        // ---- thread-local argmax (lowest index wins on ties) ----
        float bestv = md[0].x;
#pragma unroll
        for (int j = 0; j < QPT; j++) {
            bestv = fmaxf(fmaxf(bestv, fmaxf(md[j].x, md[j].y)),
                          fmaxf(md[j].z, md[j].w));
        }
        int besti = 0;
#pragma unroll
        for (int j = QPT - 1; j >= 0; j--) {
            const int ib = 4 * (j * NT + tid);
            if (md[j].w == bestv) besti = ib + 3;
            if (md[j].z == bestv) besti = ib + 2;
            if (md[j].y == bestv) besti = ib + 1;
            if (md[j].x == bestv) besti = ib + 0;
        }

        // ---- warp reduce (REDUX max value bits / min idx among holders) ----
        unsigned vb   = __float_as_uint(bestv);
        unsigned wmax = __reduce_max_sync(0xffffffffu, vb);
        unsigned imin = __reduce_min_sync(0xffffffffu,
                                          vb == wmax ? (unsigned)besti : 0xffffffffu);
        if (lane == 0) { wv[warp] = wmax; wi[warp] = imin; }
        __syncthreads();   // the ONE barrier per step

        // ---- every warp redundantly: CTA reduce + publish ----
        unsigned v2   = wv[lane];
        unsigned i2   = wi[lane];
        unsigned cmax = __reduce_max_sync(0xffffffffu, v2);
        unsigned csel = __reduce_min_sync(0xffffffffu,
                                          v2 == cmax ? i2 : 0xffffffffu);
        const int p = s & 1;
        if (lane == 0) {
            unsigned long long packed =
                ((unsigned long long)cmax << 32) |
                ((unsigned long long)(unsigned)(s + 1) << 17) |
                (unsigned)(base + (int)csel);
            st_rlx_gpu(&g_ex[b][p][rank], packed);
        }

        // ---- poll 16 peer words (all 32 lanes active; lane&15 duplicates) ----
        const unsigned long long* peer = &g_ex[b][p][lane & 15];
        const unsigned want = (unsigned)(s + 1);
        unsigned long long w;
        bool ok;
        do {
            w = ld_rlx_gpu(peer);
            ok = (((unsigned)w >> 17) == want);
        } while (!__all_sync(0xffffffffu, ok));

        unsigned gv  = (unsigned)(w >> 32);
        unsigned ggi = (unsigned)w & 0x1FFFFu;

        // Prefetch this lane's candidate coords (overlaps the reduce below).
        const float* cp = P + (size_t)ggi * 3;
        float px = cp[0], py = cp[1], pz = cp[2];

        // ---- 16-candidate reduce (REDUX pair), pick winner lane ----
        unsigned gmax = __reduce_max_sync(0xffffffffu, gv);
        unsigned gsel = __reduce_min_sync(0xffffffffu,
                                          gv == gmax ? ggi : 0xffffffffu);
        unsigned ball = __ballot_sync(0xffffffffu, gv == gmax && ggi == gsel);
        const int src = __ffs(ball) - 1;
        lx = __shfl_sync(0xffffffffu, px, src);
        ly = __shfl_sync(0xffffffffu, py, src);
        lz = __shfl_sync(0xffffffffu, pz, src);
    }
}

extern "C" void kernel_launch(void* const* d_in, const int* in_sizes, int n_in,
                              void* d_out, int out_size)
{
    (void)in_sizes; (void)n_in; (void)out_size;
    const float* pts = (const float*)d_in[0];   // point_coord (8, 131072, 3)
    float* out = (float*)d_out;                 // (8, 4096, 3)

    fps9<<<BATCH * GRP, NT>>>(pts, out);
}

// round 15
// speedup vs baseline: 11.4126x; 11.4126x over previous
#include <cuda_runtime.h>
#include <cstdint>

// FPS on GB300, round 10 = R3 (best, 8978us) + three serial-chain cuts:
//  1. named-barrier producer/consumer split: warps!=0 publish wv/wi then
//     bar.arrive(3) and go straight to barrier.cluster.arrive; only warp0
//     does bar.sync(3) before the CTA reduce (CUTLASS pattern).
//  2. output STG moved off warp0 (tid 32 emits, before its arrive).
//  3. candidate slot packed {vbits,gi | x,y | z}: post-wait reduce reads
//     LDS.128 + LDS.32 instead of 5 scalar LDS.
// Everything else is R3 verbatim: CS16 clusters (CS8 fallback), 512 thr/CTA,
// coords register-resident + SMEM copy for winner lookup, packed f32x2
// update (bit-exact: add.rn/mul.rn == scalar rn, mul-then-add order),
// REDUX max-bits/min-idx reduces (first-index tie-break), parity-buffered
// DSMEM slots, one barrier.cluster per step.

#define NPTS     131072
#define BATCH    8
#define NSAMP    4096
#define NT       512
#define BIGF     1e10f

#define ADD2(o, a, b) asm("add.rn.f32x2 %0, %1, %2;" : "=l"(o) : "l"(a), "l"(b))
#define MUL2(o, a, b) asm("mul.rn.f32x2 %0, %1, %2;" : "=l"(o) : "l"(a), "l"(b))
#define PACK2(o, lo, hi) asm("mov.b64 %0, {%1, %2};" : "=l"(o) : "f"(lo), "f"(hi))
#define UNPACK2(lo, hi, in) asm("mov.b64 {%0, %1}, %2;" : "=f"(lo), "=f"(hi) : "l"(in))

static __device__ __forceinline__ uint32_t smem_u32(const void* p) {
    uint32_t a;
    asm("{ .reg .u64 t; cvta.to.shared.u64 t, %1; cvt.u32.u64 %0, t; }"
        : "=r"(a) : "l"(p));
    return a;
}
static __device__ __forceinline__ uint32_t mapa_rank(uint32_t local, uint32_t rank) {
    uint32_t r;
    asm("mapa.shared::cluster.u32 %0, %1, %2;" : "=r"(r) : "r"(local), "r"(rank));
    return r;
}
static __device__ __forceinline__ void st_cluster_b64(uint32_t addr, unsigned long long v) {
    asm volatile("st.shared::cluster.b64 [%0], %1;" :: "r"(addr), "l"(v) : "memory");
}
static __device__ __forceinline__ void st_cluster_b32(uint32_t addr, uint32_t v) {
    asm volatile("st.shared::cluster.b32 [%0], %1;" :: "r"(addr), "r"(v) : "memory");
}
static __device__ __forceinline__ unsigned long long f2_to_u64(float a, float b) {
    unsigned long long r;
    asm("mov.b64 %0, {%1, %2};" : "=l"(r) : "f"(a), "f"(b));
    return r;
}
static __device__ __forceinline__ void cluster_arrive() {
    asm volatile("barrier.cluster.arrive.aligned;" ::: "memory");
}
static __device__ __forceinline__ void cluster_wait() {
    asm volatile("barrier.cluster.wait.aligned;" ::: "memory");
}
static __device__ __forceinline__ void bar_arrive(int id, int count) {
    asm volatile("bar.arrive %0, %1;" :: "r"(id), "r"(count) : "memory");
}
static __device__ __forceinline__ void bar_sync(int id, int count) {
    asm volatile("bar.sync %0, %1;" :: "r"(id), "r"(count) : "memory");
}

template <int CS, bool REGC>
__device__ __forceinline__ void fps_body(const float* __restrict__ pts,
                                         float* __restrict__ out)
{
    constexpr int PPC    = NPTS / CS;
    constexpr int QPT    = PPC / (4 * NT);
    constexpr int LOGPPC = (CS == 16) ? 13 : 14;

    extern __shared__ float sm[];
    float*    smx   = sm;
    float*    smy   = sm + PPC;
    float*    smz   = sm + 2 * PPC;
    unsigned* wv    = (unsigned*)(sm + 3 * PPC);   // [32] warp best value bits
    unsigned* wi    = wv + 32;                     // [32] warp best local idx
    float*    slots = (float*)(wi + 32);           // [2][CS][8] slots, 16B-aligned

    const int tid  = threadIdx.x;
    const int lane = tid & 31;
    const int warp = tid >> 5;
    uint32_t rank;
    asm("mov.u32 %0, %%cluster_ctarank;" : "=r"(rank));
    const int b = blockIdx.x / CS;
    const float* P = pts + (size_t)b * NPTS * 3;
    const int base = (int)rank * PPC;

    // Load coords: SMEM SoA copy (winner lookup) + f32x2 register cache.
    unsigned long long Xr[REGC ? 2 * QPT : 1];
    unsigned long long Yr[REGC ? 2 * QPT : 1];
    unsigned long long Zr[REGC ? 2 * QPT : 1];
#pragma unroll
    for (int j = 0; j < QPT; j++) {
        const int i0 = 4 * (j * NT + tid);
        float x[4], y[4], z[4];
#pragma unroll
        for (int k = 0; k < 4; k++) {
            const float* g = P + (size_t)(base + i0 + k) * 3;
            x[k] = g[0]; y[k] = g[1]; z[k] = g[2];
            smx[i0 + k] = x[k]; smy[i0 + k] = y[k]; smz[i0 + k] = z[k];
        }
        if (REGC) {
            PACK2(Xr[2 * j], x[0], x[1]); PACK2(Xr[2 * j + 1], x[2], x[3]);
            PACK2(Yr[2 * j], y[0], y[1]); PACK2(Yr[2 * j + 1], y[2], y[3]);
            PACK2(Zr[2 * j], z[0], z[1]); PACK2(Zr[2 * j + 1], z[2], z[3]);
        }
    }
    if (tid < 32) { wv[tid] = 0u; wi[tid] = 0xffffffffu; }  // pad warps 16..31

    float4 md[QPT];
#pragma unroll
    for (int j = 0; j < QPT; j++) md[j] = make_float4(BIGF, BIGF, BIGF, BIGF);

    __syncthreads();
    cluster_arrive();   // publish smem coords across cluster
    cluster_wait();

    float lx = P[0], ly = P[1], lz = P[2];   // reference: last_idx init = 0

    const uint32_t slots_u32 = smem_u32(slots);
    const uint32_t tgt = (uint32_t)(lane < CS ? lane : 0);
    const uint32_t rslot0 = mapa_rank(slots_u32 + rank * 32u, tgt);
    const uint32_t rslot1 = rslot0 + (uint32_t)(CS * 32);

    for (int s = 0; s < NSAMP; s++) {
        const uint32_t p = (uint32_t)(s & 1);

        // Emit BEFORE update (reference scan). Done by warp1 lane0 — keeps
        // warp0 (the critical path) free of the STG.
        if (rank == 0 && tid == 32) {
            float* o = out + ((size_t)b * NSAMP + s) * 3;
            o[0] = lx; o[1] = ly; o[2] = lz;
        }

        unsigned long long NX, NY, NZ;
        {
            float nx = -lx, ny = -ly, nz = -lz;  // x + (-l) == x - l bit-exact
            PACK2(NX, nx, nx); PACK2(NY, ny, ny); PACK2(NZ, nz, nz);
        }

        // ---- distance update (packed f32x2; mul-then-add order = reference) ----
#pragma unroll
        for (int j = 0; j < QPT; j++) {
            unsigned long long xa, xb, ya, yb, za, zb;
            if (REGC) {
                xa = Xr[2 * j]; xb = Xr[2 * j + 1];
                ya = Yr[2 * j]; yb = Yr[2 * j + 1];
                za = Zr[2 * j]; zb = Zr[2 * j + 1];
            } else {
                const int q4 = j * NT + tid;
                float4 X = ((const float4*)smx)[q4];
                float4 Y = ((const float4*)smy)[q4];
                float4 Z = ((const float4*)smz)[q4];
                PACK2(xa, X.x, X.y); PACK2(xb, X.z, X.w);
                PACK2(ya, Y.x, Y.y); PACK2(yb, Y.z, Y.w);
                PACK2(za, Z.x, Z.y); PACK2(zb, Z.z, Z.w);
            }
            unsigned long long sa, sb;
            ADD2(xa, xa, NX); MUL2(xa, xa, xa);
            ADD2(ya, ya, NY); MUL2(ya, ya, ya);
            ADD2(za, za, NZ); MUL2(za, za, za);
            ADD2(sa, xa, ya);          // (dx^2 + dy^2)
            ADD2(sa, sa, za);          // + dz^2 — same order as jnp.sum
            ADD2(xb, xb, NX); MUL2(xb, xb, xb);
            ADD2(yb, yb, NY); MUL2(yb, yb, yb);
            ADD2(zb, zb, NZ); MUL2(zb, zb, zb);
            ADD2(sb, xb, yb);
            ADD2(sb, sb, zb);
            float d0, d1, d2, d3;
            UNPACK2(d0, d1, sa);
            UNPACK2(d2, d3, sb);
            md[j].x = fminf(md[j].x, d0);
            md[j].y = fminf(md[j].y, d1);
            md[j].z = fminf(md[j].z, d2);
            md[j].w = fminf(md[j].w, d3);
        }

        // ---- thread-local argmax (lowest index wins on ties) ----
        float bestv = md[0].x;
#pragma unroll
        for (int j = 0; j < QPT; j++) {
            bestv = fmaxf(fmaxf(bestv, fmaxf(md[j].x, md[j].y)),
                          fmaxf(md[j].z, md[j].w));
        }
        int besti = 0;
#pragma unroll
        for (int j = QPT - 1; j >= 0; j--) {
            const int ib = 4 * (j * NT + tid);
            if (md[j].w == bestv) besti = ib + 3;
            if (md[j].z == bestv) besti = ib + 2;
            if (md[j].y == bestv) besti = ib + 1;
            if (md[j].x == bestv) besti = ib + 0;
        }

        // ---- warp reduce (REDUX max bits / min idx among holders) ----
        unsigned vb   = __float_as_uint(bestv);
        unsigned wmax = __reduce_max_sync(0xffffffffu, vb);
        unsigned imin = __reduce_min_sync(0xffffffffu,
                                          vb == wmax ? (unsigned)besti : 0xffffffffu);
        if (lane == 0) { wv[warp] = wmax; wi[warp] = imin; }

        if (warp != 0) {
            // Producer: signal wv/wi ready, pre-arrive at the cluster
            // barrier, and go wait. Warp0 finishes the step's critical path.
            bar_arrive(3, NT);
            cluster_arrive();
        } else {
            bar_sync(3, NT);   // wait for all 16 warps' wv/wi
            // ---- CTA reduce ----
            unsigned v2   = wv[lane];
            unsigned i2   = wi[lane];
            unsigned cmax = __reduce_max_sync(0xffffffffu, v2);
            unsigned csel = __reduce_min_sync(0xffffffffu,
                                              v2 == cmax ? i2 : 0xffffffffu);
            // ---- publish {vbits,gi | x,y | z} to slot[p][rank] everywhere ----
            if (lane < CS) {
                float cx = smx[csel], cy = smy[csel], cz = smz[csel];
                unsigned gi = (unsigned)(base + (int)csel);
                uint32_t dst = p ? rslot1 : rslot0;
                st_cluster_b64(dst,
                               (unsigned long long)cmax | ((unsigned long long)gi << 32));
                st_cluster_b64(dst + 8, f2_to_u64(cx, cy));
                st_cluster_b32(dst + 16, __float_as_uint(cz));
            }
            cluster_arrive();
        }
        cluster_wait();   // releases DSMEM stores of all CTAs

        // ---- all threads: 16-candidate reduce (LDS.128 + LDS.32) ----
        const uint32_t sl = slots_u32 + (p * CS + (uint32_t)(lane & (CS - 1))) * 32u;
        unsigned gv, ggi, xb_, yb_;
        asm volatile("ld.shared.v4.u32 {%0, %1, %2, %3}, [%4];"
                     : "=r"(gv), "=r"(ggi), "=r"(xb_), "=r"(yb_) : "r"(sl));
        unsigned zb_;
        asm volatile("ld.shared.u32 %0, [%1];" : "=r"(zb_) : "r"(sl + 16u));

        unsigned gmax = __reduce_max_sync(0xffffffffu, gv);
        unsigned gsel = __reduce_min_sync(0xffffffffu,
                                          gv == gmax ? ggi : 0xffffffffu);
        unsigned ball = __ballot_sync(0xffffffffu, gv == gmax && ggi == gsel);
        const int src = __ffs(ball) - 1;
        lx = __uint_as_float(__shfl_sync(0xffffffffu, xb_, src));
        ly = __uint_as_float(__shfl_sync(0xffffffffu, yb_, src));
        lz = __uint_as_float(__shfl_sync(0xffffffffu, zb_, src));
    }
}

__global__ void __cluster_dims__(16, 1, 1) __launch_bounds__(NT, 1)
fps16(const float* __restrict__ pts, float* __restrict__ out) {
    fps_body<16, true>(pts, out);
}
__global__ void __cluster_dims__(8, 1, 1) __launch_bounds__(NT, 1)
fps8(const float* __restrict__ pts, float* __restrict__ out) {
    fps_body<8, false>(pts, out);
}

static size_t smem_bytes(int cs) {
    int ppc = NPTS / cs;
    return (size_t)(3 * ppc + 64 + 2 * cs * 8) * sizeof(float);
}

extern "C" void kernel_launch(void* const* d_in, const int* in_sizes, int n_in,
                              void* d_out, int out_size)
{
    (void)in_sizes; (void)n_in; (void)out_size;
    const float* pts = (const float*)d_in[0];   // point_coord (8, 131072, 3)
    float* out = (float*)d_out;                 // (8, 4096, 3)

    const size_t s16 = smem_bytes(16);
    const size_t s8  = smem_bytes(8);

    cudaFuncSetAttribute(fps16, cudaFuncAttributeNonPortableClusterSizeAllowed, 1);
    cudaFuncSetAttribute(fps16, cudaFuncAttributeMaxDynamicSharedMemorySize, (int)s16);
    cudaFuncSetAttribute(fps8,  cudaFuncAttributeMaxDynamicSharedMemorySize, (int)s8);
    cudaGetLastError();

    int nc = 0;
    cudaLaunchConfig_t cfg = {};
    cfg.gridDim  = dim3(BATCH * 16, 1, 1);
    cfg.blockDim = dim3(NT, 1, 1);
    cfg.dynamicSmemBytes = s16;
    cudaLaunchAttribute at[1];
    at[0].id = cudaLaunchAttributeClusterDimension;
    at[0].val.clusterDim.x = 16;
    at[0].val.clusterDim.y = 1;
    at[0].val.clusterDim.z = 1;
    cfg.attrs = at;
    cfg.numAttrs = 1;
    cudaError_t e = cudaOccupancyMaxActiveClusters(&nc, fps16, &cfg);

    if (e == cudaSuccess && nc > 0) {
        fps16<<<BATCH * 16, NT, s16>>>(pts, out);
    } else {
        cudaGetLastError();
        fps8<<<BATCH * 8, NT, s8>>>(pts, out);
    }
}

// round 16
// speedup vs baseline: 12.8136x; 1.1228x over previous
#include <cuda_runtime.h>
#include <cstdint>

// FPS on GB300, round 11 = R3 (best, 8978us) with strictly-convergent
// micro-cuts only:
//  - final 16-candidate reduce: LDS.128 + LDS.32 slot read (was 5 scalar LDS)
//  - all lanes load slot[lane&15] (no predicated defaults)
//  - winner lane = gsel >> log2(PPC) (arithmetic, no ballot)
// Structure identical to R3: CS16 clusters (CS8 fallback), 512 thr/CTA,
// coords register-resident + SMEM copy for winner lookup, packed f32x2
// update (add.rn/mul.rn.f32x2 == scalar rn ops; mul-then-add order matches
// jnp.sum), REDUX max-bits/min-idx reduces (first-index tie-break at every
// level), parity-double-buffered DSMEM slots, ONE convergent
// barrier.cluster per step. rel_err was 0.0 for this math in rounds 1-10.

#define NPTS     131072
#define BATCH    8
#define NSAMP    4096
#define NT       512
#define BIGF     1e10f

#define ADD2(o, a, b) asm("add.rn.f32x2 %0, %1, %2;" : "=l"(o) : "l"(a), "l"(b))
#define MUL2(o, a, b) asm("mul.rn.f32x2 %0, %1, %2;" : "=l"(o) : "l"(a), "l"(b))
#define PACK2(o, lo, hi) asm("mov.b64 %0, {%1, %2};" : "=l"(o) : "f"(lo), "f"(hi))
#define UNPACK2(lo, hi, in) asm("mov.b64 {%0, %1}, %2;" : "=f"(lo), "=f"(hi) : "l"(in))

static __device__ __forceinline__ uint32_t smem_u32(const void* p) {
    uint32_t a;
    asm("{ .reg .u64 t; cvta.to.shared.u64 t, %1; cvt.u32.u64 %0, t; }"
        : "=r"(a) : "l"(p));
    return a;
}
static __device__ __forceinline__ uint32_t mapa_rank(uint32_t local, uint32_t rank) {
    uint32_t r;
    asm("mapa.shared::cluster.u32 %0, %1, %2;" : "=r"(r) : "r"(local), "r"(rank));
    return r;
}
static __device__ __forceinline__ void st_cluster_b64(uint32_t addr, unsigned long long v) {
    asm volatile("st.shared::cluster.b64 [%0], %1;" :: "r"(addr), "l"(v) : "memory");
}
static __device__ __forceinline__ void st_cluster_b32(uint32_t addr, uint32_t v) {
    asm volatile("st.shared::cluster.b32 [%0], %1;" :: "r"(addr), "r"(v) : "memory");
}
static __device__ __forceinline__ unsigned long long f2_to_u64(float a, float b) {
    unsigned long long r;
    asm("mov.b64 %0, {%1, %2};" : "=l"(r) : "f"(a), "f"(b));
    return r;
}
static __device__ __forceinline__ void cluster_barrier() {
    asm volatile("barrier.cluster.arrive.aligned;" ::: "memory");
    asm volatile("barrier.cluster.wait.aligned;" ::: "memory");
}

template <int CS, bool REGC>
__device__ __forceinline__ void fps_body(const float* __restrict__ pts,
                                         float* __restrict__ out)
{
    constexpr int PPC    = NPTS / CS;
    constexpr int QPT    = PPC / (4 * NT);
    constexpr int LOGPPC = (CS == 16) ? 13 : 14;

    extern __shared__ float sm[];
    float*    smx   = sm;
    float*    smy   = sm + PPC;
    float*    smz   = sm + 2 * PPC;
    unsigned* wv    = (unsigned*)(sm + 3 * PPC);   // [32] warp best value bits
    unsigned* wi    = wv + 32;                     // [32] warp best local idx
    float*    slots = (float*)(wi + 32);           // [2][CS][8] slots (32B ea, 16B-aligned)

    const int tid  = threadIdx.x;
    const int lane = tid & 31;
    const int warp = tid >> 5;
    uint32_t rank;
    asm("mov.u32 %0, %%cluster_ctarank;" : "=r"(rank));
    const int b = blockIdx.x / CS;
    const float* P = pts + (size_t)b * NPTS * 3;
    const int base = (int)rank * PPC;

    // Load coords: SMEM SoA copy (winner lookup) + f32x2 register cache.
    unsigned long long Xr[REGC ? 2 * QPT : 1];
    unsigned long long Yr[REGC ? 2 * QPT : 1];
    unsigned long long Zr[REGC ? 2 * QPT : 1];
#pragma unroll
    for (int j = 0; j < QPT; j++) {
        const int i0 = 4 * (j * NT + tid);
        float x[4], y[4], z[4];
#pragma unroll
        for (int k = 0; k < 4; k++) {
            const float* g = P + (size_t)(base + i0 + k) * 3;
            x[k] = g[0]; y[k] = g[1]; z[k] = g[2];
            smx[i0 + k] = x[k]; smy[i0 + k] = y[k]; smz[i0 + k] = z[k];
        }
        if (REGC) {
            PACK2(Xr[2 * j], x[0], x[1]); PACK2(Xr[2 * j + 1], x[2], x[3]);
            PACK2(Yr[2 * j], y[0], y[1]); PACK2(Yr[2 * j + 1], y[2], y[3]);
            PACK2(Zr[2 * j], z[0], z[1]); PACK2(Zr[2 * j + 1], z[2], z[3]);
        }
    }
    if (tid < 32) { wv[tid] = 0u; wi[tid] = 0xffffffffu; }  // pad warps 16..31

    float4 md[QPT];
#pragma unroll
    for (int j = 0; j < QPT; j++) md[j] = make_float4(BIGF, BIGF, BIGF, BIGF);

    __syncthreads();
    cluster_barrier();   // publish smem coords across cluster

    float lx = P[0], ly = P[1], lz = P[2];   // reference: last_idx init = 0

    const uint32_t slots_u32 = smem_u32(slots);
    const uint32_t tgt = (uint32_t)(lane < CS ? lane : 0);
    const uint32_t rslot0 = mapa_rank(slots_u32 + rank * 32u, tgt);
    const uint32_t rslot1 = rslot0 + (uint32_t)(CS * 32);

    for (int s = 0; s < NSAMP; s++) {
        const uint32_t p = (uint32_t)(s & 1);

        // Reference scan emits last_idx BEFORE the update.
        if (rank == 0 && tid == 0) {
            float* o = out + ((size_t)b * NSAMP + s) * 3;
            o[0] = lx; o[1] = ly; o[2] = lz;
        }

        unsigned long long NX, NY, NZ;
        {
            float nx = -lx, ny = -ly, nz = -lz;  // x + (-l) == x - l bit-exact
            PACK2(NX, nx, nx); PACK2(NY, ny, ny); PACK2(NZ, nz, nz);
        }

        // ---- distance update (packed f32x2; mul-then-add order = reference) ----
#pragma unroll
        for (int j = 0; j < QPT; j++) {
            unsigned long long xa, xb, ya, yb, za, zb;
            if (REGC) {
                xa = Xr[2 * j]; xb = Xr[2 * j + 1];
                ya = Yr[2 * j]; yb = Yr[2 * j + 1];
                za = Zr[2 * j]; zb = Zr[2 * j + 1];
            } else {
                const int q4 = j * NT + tid;
                float4 X = ((const float4*)smx)[q4];
                float4 Y = ((const float4*)smy)[q4];
                float4 Z = ((const float4*)smz)[q4];
                PACK2(xa, X.x, X.y); PACK2(xb, X.z, X.w);
                PACK2(ya, Y.x, Y.y); PACK2(yb, Y.z, Y.w);
                PACK2(za, Z.x, Z.y); PACK2(zb, Z.z, Z.w);
            }
            unsigned long long sa, sb;
            ADD2(xa, xa, NX); MUL2(xa, xa, xa);
            ADD2(ya, ya, NY); MUL2(ya, ya, ya);
            ADD2(za, za, NZ); MUL2(za, za, za);
            ADD2(sa, xa, ya);          // (dx^2 + dy^2)
            ADD2(sa, sa, za);          // + dz^2 — same order as jnp.sum
            ADD2(xb, xb, NX); MUL2(xb, xb, xb);
            ADD2(yb, yb, NY); MUL2(yb, yb, yb);
            ADD2(zb, zb, NZ); MUL2(zb, zb, zb);
            ADD2(sb, xb, yb);
            ADD2(sb, sb, zb);
            float d0, d1, d2, d3;
            UNPACK2(d0, d1, sa);
            UNPACK2(d2, d3, sb);
            md[j].x = fminf(md[j].x, d0);
            md[j].y = fminf(md[j].y, d1);
            md[j].z = fminf(md[j].z, d2);
            md[j].w = fminf(md[j].w, d3);
        }

        // ---- thread-local argmax: FMNMX tree + descending equality scan
        //      (lowest index wins ties => jnp.argmax tie rule) ----
        float bestv = md[0].x;
#pragma unroll
        for (int j = 0; j < QPT; j++) {
            bestv = fmaxf(fmaxf(bestv, fmaxf(md[j].x, md[j].y)),
                          fmaxf(md[j].z, md[j].w));
        }
        int besti = 0;
#pragma unroll
        for (int j = QPT - 1; j >= 0; j--) {
            const int ib = 4 * (j * NT + tid);
            if (md[j].w == bestv) besti = ib + 3;
            if (md[j].z == bestv) besti = ib + 2;
            if (md[j].y == bestv) besti = ib + 1;
            if (md[j].x == bestv) besti = ib + 0;
        }

        // ---- warp reduce (REDUX max bits / min idx among holders) ----
        unsigned vb   = __float_as_uint(bestv);
        unsigned wmax = __reduce_max_sync(0xffffffffu, vb);
        unsigned imin = __reduce_min_sync(0xffffffffu,
                                          vb == wmax ? (unsigned)besti : 0xffffffffu);
        if (lane == 0) { wv[warp] = wmax; wi[warp] = imin; }
        __syncthreads();

        // ---- CTA reduce (warp 0) + publish to all cluster CTAs ----
        if (warp == 0) {
            unsigned v2   = wv[lane];
            unsigned i2   = wi[lane];
            unsigned cmax = __reduce_max_sync(0xffffffffu, v2);
            unsigned csel = __reduce_min_sync(0xffffffffu,
                                              v2 == cmax ? i2 : 0xffffffffu);
            if (lane < CS) {
                float cx = smx[csel], cy = smy[csel], cz = smz[csel];
                unsigned gi = (unsigned)(base + (int)csel);
                uint32_t dst = p ? rslot1 : rslot0;
                st_cluster_b64(dst,
                               (unsigned long long)cmax | ((unsigned long long)gi << 32));
                st_cluster_b64(dst + 8, f2_to_u64(cx, cy));
                st_cluster_b32(dst + 16, __float_as_uint(cz));
            }
        }

        // One convergent cluster barrier per step: releases the DSMEM stores,
        // protects the parity-buffered slots.
        cluster_barrier();

        // ---- all threads: 16-candidate reduce; LDS.128 + LDS.32 slot read ----
        const uint32_t sl =
            slots_u32 + (p * CS + (uint32_t)(lane & (CS - 1))) * 32u;
        unsigned gv, ggi, xb_, yb_;
        asm volatile("ld.shared.v4.u32 {%0, %1, %2, %3}, [%4];"
                     : "=r"(gv), "=r"(ggi), "=r"(xb_), "=r"(yb_) : "r"(sl));
        unsigned zb_;
        asm volatile("ld.shared.u32 %0, [%1];" : "=r"(zb_) : "r"(sl + 16u));

        unsigned gmax = __reduce_max_sync(0xffffffffu, gv);
        unsigned gsel = __reduce_min_sync(0xffffffffu,
                                          gv == gmax ? ggi : 0xffffffffu);
        const int wl = (int)(gsel >> LOGPPC);   // winning rank == slot index
        lx = __uint_as_float(__shfl_sync(0xffffffffu, xb_, wl));
        ly = __uint_as_float(__shfl_sync(0xffffffffu, yb_, wl));
        lz = __uint_as_float(__shfl_sync(0xffffffffu, zb_, wl));
    }
}

__global__ void __cluster_dims__(16, 1, 1) __launch_bounds__(NT, 1)
fps16(const float* __restrict__ pts, float* __restrict__ out) {
    fps_body<16, true>(pts, out);
}
__global__ void __cluster_dims__(8, 1, 1) __launch_bounds__(NT, 1)
fps8(const float* __restrict__ pts, float* __restrict__ out) {
    fps_body<8, false>(pts, out);
}

static size_t smem_bytes(int cs) {
    int ppc = NPTS / cs;
    return (size_t)(3 * ppc + 64 + 2 * cs * 8) * sizeof(float);
}

extern "C" void kernel_launch(void* const* d_in, const int* in_sizes, int n_in,
                              void* d_out, int out_size)
{
    (void)in_sizes; (void)n_in; (void)out_size;
    const float* pts = (const float*)d_in[0];   // point_coord (8, 131072, 3)
    float* out = (float*)d_out;                 // (8, 4096, 3)

    const size_t s16 = smem_bytes(16);
    const size_t s8  = smem_bytes(8);

    cudaFuncSetAttribute(fps16, cudaFuncAttributeNonPortableClusterSizeAllowed, 1);
    cudaFuncSetAttribute(fps16, cudaFuncAttributeMaxDynamicSharedMemorySize, (int)s16);
    cudaFuncSetAttribute(fps8,  cudaFuncAttributeMaxDynamicSharedMemorySize, (int)s8);
    cudaGetLastError();

    int nc = 0;
    cudaLaunchConfig_t cfg = {};
    cfg.gridDim  = dim3(BATCH * 16, 1, 1);
    cfg.blockDim = dim3(NT, 1, 1);
    cfg.dynamicSmemBytes = s16;
    cudaLaunchAttribute at[1];
    at[0].id = cudaLaunchAttributeClusterDimension;
    at[0].val.clusterDim.x = 16;
    at[0].val.clusterDim.y = 1;
    at[0].val.clusterDim.z = 1;
    cfg.attrs = at;
    cfg.numAttrs = 1;
    cudaError_t e = cudaOccupancyMaxActiveClusters(&nc, fps16, &cfg);

    if (e == cudaSuccess && nc > 0) {
        fps16<<<BATCH * 16, NT, s16>>>(pts, out);
    } else {
        cudaGetLastError();
        fps8<<<BATCH * 8, NT, s8>>>(pts, out);
    }
}